// round 1
// baseline (speedup 1.0000x reference)
#include <cuda_runtime.h>

typedef unsigned long long u64;
typedef unsigned int u32;

#define T_FRAMES 5
#define WS 8
#define HEADS 6
#define DIM 192
#define HDIM 32
#define NTOK 320
#define KROW 36   // padded row (floats) for K/V smem tiles

// scratch: per-window attention output, [wb][n][DIM], sized for B=2
__device__ float g_scratch[2 * 64 * NTOK * DIM];

// ---------------- f32x2 helpers (sm_100+ packed fp32) ----------------
__device__ __forceinline__ u64 pack2(float lo, float hi) {
    u64 r; asm("mov.b64 %0,{%1,%2};" : "=l"(r) : "f"(lo), "f"(hi)); return r;
}
__device__ __forceinline__ void unpack2(u64 v, float &lo, float &hi) {
    asm("mov.b64 {%0,%1},%2;" : "=f"(lo), "=f"(hi) : "l"(v));
}
__device__ __forceinline__ u64 add2(u64 a, u64 b) {
    u64 r; asm("add.rn.f32x2 %0,%1,%2;" : "=l"(r) : "l"(a), "l"(b)); return r;
}
__device__ __forceinline__ void fma2(u64 &d, u64 a, u64 b) {
    asm("fma.rn.f32x2 %0,%1,%2,%0;" : "+l"(d) : "l"(a), "l"(b));
}
// 16B smem load + 2 packed FMAs: d0 += q0*k[0:2], d1 += q1*k[2:4]
__device__ __forceinline__ void dot_frag(u64 &d0, u64 &d1, u64 q0, u64 q1, u32 sa) {
    asm volatile("{\n\t.reg .b64 t0,t1;\n\t"
        "ld.shared.v2.b64 {t0,t1},[%2];\n\t"
        "fma.rn.f32x2 %0,%3,t0,%0;\n\t"
        "fma.rn.f32x2 %1,%4,t1,%1;\n\t}"
        : "+l"(d0), "+l"(d1) : "r"(sa), "l"(q0), "l"(q1));
}
// 16B smem load + 2 packed FMAs with broadcast multiplier pp
__device__ __forceinline__ void av_frag(u64 &a0, u64 &a1, u64 pp, u32 sa) {
    asm volatile("{\n\t.reg .b64 t0,t1;\n\t"
        "ld.shared.v2.b64 {t0,t1},[%2];\n\t"
        "fma.rn.f32x2 %0,t0,%3,%0;\n\t"
        "fma.rn.f32x2 %1,t1,%3,%1;\n\t}"
        : "+l"(a0), "+l"(a1) : "r"(sa), "l"(pp));
}
__device__ __forceinline__ u64 lds64(u32 sa) {
    u64 r; asm volatile("ld.shared.b64 %0,[%1];" : "=l"(r) : "r"(sa)); return r;
}

// ---------------- attention kernel ----------------
// smem layout (floats): K tile | V tile | bias column | token meta
#define SM_V    (NTOK * KROW)
#define SM_BIAS (2 * NTOK * KROW)
#define SM_META (SM_BIAS + 1185)
#define ATTN_SMEM ((SM_META + NTOK) * 4)

__global__ void __launch_bounds__(320)
attn_kernel(const float* __restrict__ qkv, const float* __restrict__ bias_table)
{
    extern __shared__ float sm[];
    float* k_s    = sm;
    float* v_s    = sm + SM_V;
    float* bias_s = sm + SM_BIAS;
    int*   meta_s = (int*)(sm + SM_META);

    const int head = blockIdx.y;
    const int wb   = blockIdx.x;          // b*64 + widx
    const int b    = wb >> 6;
    const int widx = wb & 63;
    const int hw = widx >> 3, ww = widx & 7;

    const int i  = threadIdx.x;           // query token 0..319
    const int t  = i >> 6;
    const int hs = (i >> 3) & 7;
    const int wsv = i & 7;
    const int Hp = hw * 8 + hs;           // shifted-frame coords
    const int Wp = ww * 8 + wsv;
    const int h = (Hp + 4) & 63;          // un-shift: roll(-4) gather
    const int w = (Wp + 4) & 63;
    // Swin shift mask regions (computed, not loaded)
    const int rh = (Hp < 56) ? 0 : ((Hp < 60) ? 1 : 2);
    const int rw = (Wp < 56) ? 0 : ((Wp < 60) ? 1 : 2);
    const int r_i = rh * 3 + rw;
    const int bj  = t * 15 + hs + wsv;    // rel-bias component
    meta_s[i] = bj | (r_i << 8);

    const int row = ((b * T_FRAMES + t) << 12) + (h << 6) + w;
    const float* qp = qkv + (size_t)row * (3 * DIM) + head * HDIM;

    // K, V rows into smem (padded rows)
    {
        float4* kd = (float4*)(k_s + i * KROW);
        float4* vd = (float4*)(v_s + i * KROW);
        const float4* ksrc = (const float4*)(qp + DIM);
        const float4* vsrc = (const float4*)(qp + 2 * DIM);
        #pragma unroll
        for (int m = 0; m < 8; ++m) kd[m] = ksrc[m];
        #pragma unroll
        for (int m = 0; m < 8; ++m) vd[m] = vsrc[m];
    }
    const float LOG2E = 1.4426950408889634f;
    for (int idx = i; idx < 1185; idx += NTOK)
        bias_s[idx] = bias_table[idx * HEADS + head] * LOG2E;

    // q into registers, pre-scaled by SCALE * log2(e)
    const float qs_f = 0.17677669529663687f * LOG2E;
    u64 q[16];
    {
        const float4* qv = (const float4*)qp;
        #pragma unroll
        for (int m = 0; m < 8; ++m) {
            float4 f = qv[m];
            q[2 * m]     = pack2(f.x * qs_f, f.y * qs_f);
            q[2 * m + 1] = pack2(f.z * qs_f, f.w * qs_f);
        }
    }
    __syncthreads();

    const u32 kbase = (u32)__cvta_generic_to_shared(k_s);
    const u32 vbase = (u32)__cvta_generic_to_shared(v_s);

    u64 acc[16];
    #pragma unroll
    for (int m = 0; m < 16; ++m) acc[m] = 0ULL;
    float l = 0.f;
    const int a_i = bj + 112;

    #pragma unroll 2
    for (int j = 0; j < NTOK; ++j) {
        const int mj = meta_s[j];
        const u32 ka = kbase + j * (KROW * 4);
        u64 d0 = 0, d1 = 0, d2 = 0, d3 = 0;
        dot_frag(d0, d1, q[0],  q[1],  ka);
        dot_frag(d2, d3, q[2],  q[3],  ka + 16);
        dot_frag(d0, d1, q[4],  q[5],  ka + 32);
        dot_frag(d2, d3, q[6],  q[7],  ka + 48);
        dot_frag(d0, d1, q[8],  q[9],  ka + 64);
        dot_frag(d2, d3, q[10], q[11], ka + 80);
        dot_frag(d0, d1, q[12], q[13], ka + 96);
        dot_frag(d2, d3, q[14], q[15], ka + 112);
        u64 e = add2(add2(d0, d1), add2(d2, d3));
        float sx, sy; unpack2(e, sx, sy);
        const float s = sx + sy + bias_s[a_i - (mj & 255)];
        float p; asm("ex2.approx.ftz.f32 %0,%1;" : "=f"(p) : "f"(s));
        p = ((mj >> 8) == r_i) ? p : 0.f;   // mask: exclude cross-region keys
        l += p;
        const u64 pp = pack2(p, p);
        const u32 va = vbase + j * (KROW * 4);
        av_frag(acc[0],  acc[1],  pp, va);
        av_frag(acc[2],  acc[3],  pp, va + 16);
        av_frag(acc[4],  acc[5],  pp, va + 32);
        av_frag(acc[6],  acc[7],  pp, va + 48);
        av_frag(acc[8],  acc[9],  pp, va + 64);
        av_frag(acc[10], acc[11], pp, va + 80);
        av_frag(acc[12], acc[13], pp, va + 96);
        av_frag(acc[14], acc[15], pp, va + 112);
    }

    const float inv = 1.0f / l;
    float4* op = (float4*)(g_scratch + ((size_t)(wb * NTOK + i)) * DIM + head * HDIM);
    #pragma unroll
    for (int m = 0; m < 8; ++m) {
        float x0, x1, x2, x3;
        unpack2(acc[2 * m],     x0, x1);
        unpack2(acc[2 * m + 1], x2, x3);
        op[m] = make_float4(x0 * inv, x1 * inv, x2 * inv, x3 * inv);
    }
}

// ---------------- projection + window-reverse kernel ----------------
#define WPAD 194
#define OPAD 196
#define PROJ_SMEM ((DIM * WPAD + 64 * OPAD) * 4)

__global__ void __launch_bounds__(256)
proj_kernel(const float* __restrict__ pw, const float* __restrict__ pb,
            float* __restrict__ out, int nchunks)
{
    extern __shared__ float sm[];
    float* Wsh = sm;                 // [192][194]
    float* o_s = sm + DIM * WPAD;    // [64][196]
    const int tid = threadIdx.x, tx = tid & 31, ty = tid >> 5;

    // stage full W (row-major, k-contiguous)
    for (int idx = tid * 4; idx < DIM * DIM; idx += 1024) {
        float4 v = *(const float4*)(pw + idx);
        const int c = idx / DIM, k = idx - c * DIM;
        float* dst = Wsh + c * WPAD + k;
        dst[0] = v.x; dst[1] = v.y; dst[2] = v.z; dst[3] = v.w;
    }
    float pbv[6];
    #pragma unroll
    for (int j = 0; j < 6; ++j) pbv[j] = pb[j * 32 + tx];

    const u32 wbase = (u32)__cvta_generic_to_shared(Wsh) + tx * (WPAD * 4);
    const u32 obase = (u32)__cvta_generic_to_shared(o_s) + ty * (8 * OPAD * 4);

    for (int ci = blockIdx.x; ci < nchunks; ci += gridDim.x) {
        __syncthreads();
        const float* src = g_scratch + (size_t)ci * (64 * DIM);  // ci = wb*5 + t
        for (int idx = tid * 4; idx < 64 * DIM; idx += 1024) {
            float4 v = *(const float4*)(src + idx);
            const int tok = idx / DIM, k = idx - tok * DIM;
            *(float4*)(o_s + tok * OPAD + k) = v;
        }
        __syncthreads();

        u64 acc[8][6];
        #pragma unroll
        for (int m = 0; m < 8; ++m)
            #pragma unroll
            for (int j = 0; j < 6; ++j) acc[m][j] = 0ULL;

        #pragma unroll 2
        for (int k = 0; k < DIM; k += 2) {
            u64 w2[6], o2[8];
            #pragma unroll
            for (int j = 0; j < 6; ++j)
                w2[j] = lds64(wbase + (u32)(j * 32 * WPAD * 4) + k * 4);
            #pragma unroll
            for (int m = 0; m < 8; ++m)
                o2[m] = lds64(obase + (u32)(m * OPAD * 4) + k * 4);
            #pragma unroll
            for (int m = 0; m < 8; ++m)
                #pragma unroll
                for (int j = 0; j < 6; ++j) fma2(acc[m][j], o2[m], w2[j]);
        }

        const int wbid = ci / 5, t = ci % 5;
        const int b = wbid >> 6, widx = wbid & 63;
        const int hw = widx >> 3, ww = widx & 7;
        #pragma unroll
        for (int m = 0; m < 8; ++m) {
            const int mt = ty * 8 + m;
            const int hs = mt >> 3, wsv = mt & 7;
            const int h = (hw * 8 + hs + 4) & 63;
            const int w = (ww * 8 + wsv + 4) & 63;
            float* orow = out + ((size_t)((b * T_FRAMES + t) * 4096 + h * 64 + w)) * DIM;
            #pragma unroll
            for (int j = 0; j < 6; ++j) {
                float lo, hi; unpack2(acc[m][j], lo, hi);
                orow[j * 32 + tx] = lo + hi + pbv[j];
            }
        }
    }
}

// ---------------- launch ----------------
extern "C" void kernel_launch(void* const* d_in, const int* in_sizes, int n_in,
                              void* d_out, int out_size)
{
    const float* qkv        = (const float*)d_in[0];
    const float* bias_table = (const float*)d_in[1];
    const float* pw         = (const float*)d_in[2];
    const float* pb         = (const float*)d_in[3];
    float* out = (float*)d_out;

    int B = in_sizes[0] / (T_FRAMES * 64 * 64 * 3 * DIM);
    if (B < 1) B = 1;
    if (B > 2) B = 2;   // scratch sized for B=2 (problem fixed at B=2)

    cudaFuncSetAttribute(attn_kernel, cudaFuncAttributeMaxDynamicSharedMemorySize, ATTN_SMEM);
    cudaFuncSetAttribute(proj_kernel, cudaFuncAttributeMaxDynamicSharedMemorySize, PROJ_SMEM);

    dim3 ag(B * 64, HEADS);
    attn_kernel<<<ag, NTOK, ATTN_SMEM>>>(qkv, bias_table);

    const int nchunks = B * 64 * T_FRAMES;
    proj_kernel<<<nchunks, 256, PROJ_SMEM>>>(pw, pb, out, nchunks);
}